// round 5
// baseline (speedup 1.0000x reference)
#include <cuda_runtime.h>
#include <cstdint>

// RAPiD decode: raw (64,18,128,128) f32 -> pred (64, 3*128*128, 6) f32
// per cell: px=(sig(r0)+x)/W*img_w ; py=(sig(r1)+y)/H*img_h
//           pw=exp(r2)*aw ; ph=exp(r3)*ah ; pa=sig(r4)*360-180 ; conf=sig(r5)
// VEC=4, warp-scoped smem transpose (no block barrier), coalesced both ways.

static constexpr int NB = 64;
static constexpr int NA = 3;
static constexpr int NH = 128;
static constexpr int NW = 128;
static constexpr int HW = NH * NW;          // 16384
static constexpr int CELLS = NB * NA * HW;  // 3,145,728
static constexpr int TPB = 256;
static constexpr int VEC = 4;
static constexpr int CPB = TPB * VEC;       // 1024 cells per block
static constexpr int WARP_CELLS = 32 * VEC;            // 128 cells per warp
static constexpr int WARP_SPAN  = WARP_CELLS * 6;      // 768 floats per warp

__device__ __forceinline__ float htanh(float x) {
    float y;
    asm("tanh.approx.f32 %0, %1;" : "=f"(y) : "f"(x));
    return y;
}
// sigmoid(x) = 0.5*tanh(x/2) + 0.5   (1 MUFU + 1 FMA)
__device__ __forceinline__ float fsig(float x) {
    return fmaf(htanh(0.5f * x), 0.5f, 0.5f);
}

__global__ void __launch_bounds__(TPB) rapid_decode_kernel(
    const float* __restrict__ raw,
    const float* __restrict__ anchors,
    const int* __restrict__ p_img_h,
    const int* __restrict__ p_img_w,
    float* __restrict__ out)
{
    __shared__ float s[CPB * 6];   // 24 KB, cell-major

    const int tid  = threadIdx.x;
    const int warp = tid >> 5;
    const int lane = tid & 31;
    const int c0   = blockIdx.x * CPB + tid * VEC;  // first of 4 consecutive cells

    const int w0  = c0 & (NW - 1);          // multiple of 4; no row crossing
    const int h   = (c0 >> 7) & (NH - 1);
    const int ahw = c0 >> 14;               // b*3 + a (constant over the 4)
    const int a   = ahw % 3;
    const int b   = ahw / 3;

    const float sw = (float)__ldg(p_img_w) * (1.0f / (float)NW);
    const float sh = (float)__ldg(p_img_h) * (1.0f / (float)NH);
    const float aw = __ldg(anchors + 2 * a);
    const float ah = __ldg(anchors + 2 * a + 1);

    // input: raw[b, a*6 + f, h, w], channel stride HW; float4 over w
    const size_t in_base = ((size_t)(b * 18 + a * 6) << 14) + (size_t)(c0 & (HW - 1));
    const float4* p = reinterpret_cast<const float4*>(raw + in_base);
    const float4 r0 = __ldg(p);
    const float4 r1 = __ldg(p + 1 * (HW / 4));
    const float4 r2 = __ldg(p + 2 * (HW / 4));
    const float4 r3 = __ldg(p + 3 * (HW / 4));
    const float4 r4 = __ldg(p + 4 * (HW / 4));
    const float4 r5 = __ldg(p + 5 * (HW / 4));

    const float fh = (float)h;
    const float x0[4] = { r0.x, r0.y, r0.z, r0.w };
    const float x1[4] = { r1.x, r1.y, r1.z, r1.w };
    const float x2[4] = { r2.x, r2.y, r2.z, r2.w };
    const float x3[4] = { r3.x, r3.y, r3.z, r3.w };
    const float x4[4] = { r4.x, r4.y, r4.z, r4.w };
    const float x5[4] = { r5.x, r5.y, r5.z, r5.w };

    // stage 24 contiguous floats at s[24*tid] -> 6x STS.128
    float* sp = s + tid * 24;
    #pragma unroll
    for (int i = 0; i < 4; ++i) {
        float4 oa, ob;
        oa.x = (fsig(x0[i]) + (float)(w0 + i)) * sw;   // px
        oa.y = (fsig(x1[i]) + fh) * sh;                // py
        oa.z = __expf(x2[i]) * aw;                     // pw
        oa.w = __expf(x3[i]) * ah;                     // ph
        ob.x = fsig(x4[i]) * 360.0f - 180.0f;          // pa
        ob.y = fsig(x5[i]);                            // conf
        if (i & 1) {
            // odd cells start at +6 floats (not 16B aligned) -> write as 2+4? No:
            // cells i=0..3 at sp + 6*i; pairs (0,1) and (2,3) form 12-float blocks.
            // handled below via pairwise packing.
        }
        // pack pairwise: store via temporary register block
        sp[6 * i + 0] = oa.x; sp[6 * i + 1] = oa.y; sp[6 * i + 2] = oa.z;
        sp[6 * i + 3] = oa.w; sp[6 * i + 4] = ob.x; sp[6 * i + 5] = ob.y;
    }

    __syncwarp();

    // flush warp's own contiguous 768-float span: 6x (LDS.128 + STG.128)
    const float4* sv = reinterpret_cast<const float4*>(s + warp * WARP_SPAN);
    float4* ov = reinterpret_cast<float4*>(
        out + ((size_t)blockIdx.x * CPB + (size_t)warp * WARP_CELLS) * 6);
    #pragma unroll
    for (int j = 0; j < WARP_SPAN / 4 / 32; ++j) {   // 6 iters
        const int q = lane + j * 32;
        __stcs(ov + q, sv[q]);
    }
}

extern "C" void kernel_launch(void* const* d_in, const int* in_sizes, int n_in,
                              void* d_out, int out_size)
{
    const float* raw     = (const float*)d_in[0];
    const float* anchors = (const float*)d_in[1];
    const int*   img_h   = (const int*)d_in[2];
    const int*   img_w   = (const int*)d_in[3];
    float* out = (float*)d_out;

    const int blocks = CELLS / CPB;  // 3072
    rapid_decode_kernel<<<blocks, TPB>>>(raw, anchors, img_h, img_w, out);
}

// round 6
// speedup vs baseline: 1.0996x; 1.0996x over previous
#include <cuda_runtime.h>
#include <cstdint>

// RAPiD decode: raw (64,18,128,128) f32 -> pred (64, 3*128*128, 6) f32
// per cell: px=(sig(r0)+x)/W*img_w ; py=(sig(r1)+y)/H*img_h
//           pw=exp(r2)*aw ; ph=exp(r3)*ah ; pa=sig(r4)*360-180 ; conf=sig(r5)
// R4 structure (VEC=2, cell-major smem, STS.128 x3, coalesced flush) with
// warp-scoped sync (transpose is warp-local) and full occupancy.

static constexpr int NB = 64;
static constexpr int NA = 3;
static constexpr int NH = 128;
static constexpr int NW = 128;
static constexpr int HW = NH * NW;          // 16384
static constexpr int CELLS = NB * NA * HW;  // 3,145,728
static constexpr int TPB = 256;
static constexpr int VEC = 2;
static constexpr int CPB = TPB * VEC;       // 512 cells per block
static constexpr int WARP_CELLS = 32 * VEC;        // 64 cells per warp
static constexpr int WARP_SPAN  = WARP_CELLS * 6;  // 384 floats per warp

__device__ __forceinline__ float htanh(float x) {
    float y;
    asm("tanh.approx.f32 %0, %1;" : "=f"(y) : "f"(x));
    return y;
}
// sigmoid(x) = 0.5*tanh(x/2) + 0.5   (1 MUFU + 1 FMA)
__device__ __forceinline__ float fsig(float x) {
    return fmaf(htanh(0.5f * x), 0.5f, 0.5f);
}

__global__ void __launch_bounds__(TPB, 8) rapid_decode_kernel(
    const float* __restrict__ raw,
    const float* __restrict__ anchors,
    const int* __restrict__ p_img_h,
    const int* __restrict__ p_img_w,
    float* __restrict__ out)
{
    __shared__ float s[CPB * 6];   // 12 KB, cell-major

    const int tid  = threadIdx.x;
    const int warp = tid >> 5;
    const int lane = tid & 31;
    const int c0   = blockIdx.x * CPB + tid * VEC;  // first of 2 consecutive cells

    const int w0  = c0 & (NW - 1);          // even; pair stays within one row
    const int h   = (c0 >> 7) & (NH - 1);
    const int ahw = c0 >> 14;               // b*3 + a (constant over the pair)
    const int a   = ahw % 3;
    const int b   = ahw / 3;

    const float sw = (float)__ldg(p_img_w) * (1.0f / (float)NW);
    const float sh = (float)__ldg(p_img_h) * (1.0f / (float)NH);
    const float aw = __ldg(anchors + 2 * a);
    const float ah = __ldg(anchors + 2 * a + 1);

    // input: raw[b, a*6 + f, h, w], channel stride HW; float2 over w, streaming
    const size_t in_base = ((size_t)(b * 18 + a * 6) << 14) + (size_t)(c0 & (HW - 1));
    const float2* p = reinterpret_cast<const float2*>(raw + in_base);
    const float2 r0 = __ldcs(p);
    const float2 r1 = __ldcs(p + 1 * (HW / 2));
    const float2 r2 = __ldcs(p + 2 * (HW / 2));
    const float2 r3 = __ldcs(p + 3 * (HW / 2));
    const float2 r4 = __ldcs(p + 4 * (HW / 2));
    const float2 r5 = __ldcs(p + 5 * (HW / 2));

    const float fh = (float)h;

    float4 o0, o1, o2;
    // cell 0: px py pw ph | pa conf
    o0.x = (fsig(r0.x) + (float)(w0 + 0)) * sw;
    o0.y = (fsig(r1.x) + fh) * sh;
    o0.z = __expf(r2.x) * aw;
    o0.w = __expf(r3.x) * ah;
    o1.x = fsig(r4.x) * 360.0f - 180.0f;
    o1.y = fsig(r5.x);
    // cell 1
    o1.z = (fsig(r0.y) + (float)(w0 + 1)) * sw;
    o1.w = (fsig(r1.y) + fh) * sh;
    o2.x = __expf(r2.y) * aw;
    o2.y = __expf(r3.y) * ah;
    o2.z = fsig(r4.y) * 360.0f - 180.0f;
    o2.w = fsig(r5.y);

    // stage: 12 contiguous floats at s[12*tid] -> 3x STS.128, conflict-free.
    // Thread's span lies entirely inside its warp's 384-float region.
    float4* sp = reinterpret_cast<float4*>(s + tid * 12);
    sp[0] = o0;
    sp[1] = o1;
    sp[2] = o2;

    __syncwarp();

    // flush warp's own contiguous 384-float span: 3x (LDS.128 + STG.128)
    const float4* sv = reinterpret_cast<const float4*>(s + warp * WARP_SPAN);
    float4* ov = reinterpret_cast<float4*>(
        out + ((size_t)blockIdx.x * CPB + (size_t)warp * WARP_CELLS) * 6);
    #pragma unroll
    for (int j = 0; j < WARP_SPAN / 4 / 32; ++j) {   // 3 iters
        const int q = lane + j * 32;
        __stcs(ov + q, sv[q]);
    }
}

extern "C" void kernel_launch(void* const* d_in, const int* in_sizes, int n_in,
                              void* d_out, int out_size)
{
    const float* raw     = (const float*)d_in[0];
    const float* anchors = (const float*)d_in[1];
    const int*   img_h   = (const int*)d_in[2];
    const int*   img_w   = (const int*)d_in[3];
    float* out = (float*)d_out;

    const int blocks = CELLS / CPB;  // 6144
    rapid_decode_kernel<<<blocks, TPB>>>(raw, anchors, img_h, img_w, out);
}